// round 7
// baseline (speedup 1.0000x reference)
#include <cuda_runtime.h>
#include <cuda_bf16.h>
#include <math.h>

// pred[b] = sigmoid(gb + data[b,:].bias + || data[b,:] @ embed ||^2)
//   (the (B,F,F) Gram double-sum collapses to the squared norm of s = x @ V)
//
// Grid = 128 blocks (fg 0..15 x bg 0..7), 256 threads, one wave.
// Block (fg, bg): 8 batch rows x 128 features x all 64 dims.
//   - x tile in smem; butterfly (SHFL.XOR) reduces the 16 feature slices
//   - partials accumulated into device scratch via relaxed RED.ADD
//   - HIERARCHICAL finish: one acq_rel ticket PER batch group (8 counters on
//     distinct cache lines). The 16th block of each group finishes that
//     group's 8 rows (2KB readback) and resets its slice + counter, so the 8
//     group-finishers run in parallel and each waits only on 16 blocks.

#define F_NUM   2048
#define D_DIM   64
#define BATCH   64
#define THREADS 256
#define BGC     8          // batch groups (8 rows each)
#define FGC     16         // feature groups per batch group
#define FPB     128        // features per block
#define BPB     8          // batch rows per block

__device__ float        g_s[BATCH][D_DIM];   // zero-init; re-zeroed by finishers
__device__ float        g_lin[BATCH];
__device__ unsigned int g_counter[BGC * 32]; // one counter per 128B line

__global__ __launch_bounds__(THREADS, 1)
void KTM_22110491640579_kernel(const float* __restrict__ data,
                               const float* __restrict__ embed,
                               const float* __restrict__ bias,
                               const float* __restrict__ gbias,
                               float* __restrict__ out) {
    __shared__ float4 xs4[BPB][FPB / 4];      // 4 KB x tile [8][128]
    __shared__ unsigned int s_ticket;

    const int tid  = threadIdx.x;
    const int fg   = blockIdx.x & (FGC - 1);  // 0..15
    const int bg   = blockIdx.x >> 4;         // 0..7
    const int f0   = fg * FPB;
    const int b0   = bg * BPB;
    const int w    = tid >> 5;                // warp 0..7
    const int lane = tid & 31;

    // ---- prefetch bias for the linear term (overlaps with x staging) ----
    float bv[4];
    #pragma unroll
    for (int k = 0; k < 4; ++k) bv[k] = bias[f0 + lane + 32 * k];

    // ---- stage x tile: 8 rows x 128 floats, one float4 per thread ----
    xs4[w][lane] = ((const float4*)(data + (size_t)(b0 + w) * F_NUM + f0))[lane];
    __syncthreads();
    const float* xs = (const float*)xs4;      // [b][f], stride 128

    // ---- main loop ----
    // dq = half-warp-selected quad of the 64-dim s vector (16 quads total)
    // fs = lane bits 0..3 -> 16 slices x 8 features
    const int dq = (w << 1) | (lane >> 4);    // 0..15
    const int fs = lane & 15;                 // 0..15
    const float4* V4 = ((const float4*)embed) + ((size_t)(f0 + fs * 8) * 16 + dq);

    float4 acc[BPB];
    #pragma unroll
    for (int b = 0; b < BPB; ++b) acc[b] = make_float4(0.f, 0.f, 0.f, 0.f);

    #pragma unroll
    for (int j = 0; j < 8; ++j) {
        const float4 v = V4[(size_t)j * 16];          // coalesced, L2-hot
        #pragma unroll
        for (int b = 0; b < BPB; ++b) {
            const float x = xs[b * FPB + fs * 8 + j]; // smem broadcast
            acc[b].x = fmaf(x, v.x, acc[b].x);
            acc[b].y = fmaf(x, v.y, acc[b].y);
            acc[b].z = fmaf(x, v.z, acc[b].z);
            acc[b].w = fmaf(x, v.w, acc[b].w);
        }
    }

    // ---- linear term: warp w handles batch row w, full-warp shfl reduce ----
    {
        float l = 0.f;
        #pragma unroll
        for (int k = 0; k < 4; ++k)
            l = fmaf(xs[w * FPB + lane + 32 * k], bv[k], l);
        #pragma unroll
        for (int off = 16; off >= 1; off >>= 1)
            l += __shfl_down_sync(0xffffffffu, l, off);
        if (lane == 0) atomicAdd(&g_lin[b0 + w], l);  // relaxed RED.ADD
    }

    // ---- butterfly-reduce acc over fs (lane bits 0..3); dq bit untouched ----
    #pragma unroll
    for (int off = 1; off < 16; off <<= 1) {
        #pragma unroll
        for (int b = 0; b < BPB; ++b) {
            acc[b].x += __shfl_xor_sync(0xffffffffu, acc[b].x, off);
            acc[b].y += __shfl_xor_sync(0xffffffffu, acc[b].y, off);
            acc[b].z += __shfl_xor_sync(0xffffffffu, acc[b].z, off);
            acc[b].w += __shfl_xor_sync(0xffffffffu, acc[b].w, off);
        }
    }
    // every lane now holds the full fs-sum for its dq; 8 lanes per half-warp
    // each emit one batch row's quad (parallel REDs).
    if (fs < BPB) {
        const float4 a = acc[fs];
        float* dst = &g_s[b0 + fs][dq * 4];
        atomicAdd(dst + 0, a.x);
        atomicAdd(dst + 1, a.y);
        atomicAdd(dst + 2, a.z);
        atomicAdd(dst + 3, a.w);
    }

    // ---- per-group acq_rel ticket (release our REDs / acquire others') ----
    __syncthreads();
    if (tid == 0) {
        unsigned int old;
        asm volatile("atom.acq_rel.gpu.global.add.u32 %0, [%1], 1;"
                     : "=r"(old) : "l"(&g_counter[bg * 32]) : "memory");
        s_ticket = old;
    }
    __syncthreads();
    if (s_ticket != (unsigned)(FGC - 1)) return;

    // ---- group finisher: 8 rows of THIS batch group only (2KB readback) ----
    {
        const int b = b0 + w;                 // warp w -> batch row b0+w
        const float2 v = __ldcg(((const float2*)g_s[b]) + lane);  // dims 2*lane..
        float ss = fmaf(v.x, v.x, v.y * v.y);
        #pragma unroll
        for (int off = 16; off >= 1; off >>= 1)
            ss += __shfl_down_sync(0xffffffffu, ss, off);
        if (lane == 0) {
            const float z = __ldcg(&gbias[0]) + __ldcg(&g_lin[b]) + ss;
            out[b] = 1.0f / (1.0f + __expf(-z));
            g_lin[b] = 0.f;                   // reset for next replay
        }
        if (lane < 16)                        // reset s slice (16 float4 = 64 f)
            ((float4*)g_s[b])[lane] = make_float4(0.f, 0.f, 0.f, 0.f);
        if (tid == 0) g_counter[bg * 32] = 0u;
    }
}

extern "C" void kernel_launch(void* const* d_in, const int* in_sizes, int n_in,
                              void* d_out, int out_size) {
    const float* data  = (const float*)d_in[0];   // (64, 2048)
    const float* embed = (const float*)d_in[1];   // (2048, 64)
    const float* bias  = (const float*)d_in[2];   // (2048, 1)
    const float* gb    = (const float*)d_in[3];   // (1, 1)
    float* out = (float*)d_out;                   // (64,)
    (void)in_sizes; (void)n_in; (void)out_size;

    KTM_22110491640579_kernel<<<FGC * BGC, THREADS>>>(data, embed, bias, gb, out);
}

// round 9
// speedup vs baseline: 1.1026x; 1.1026x over previous
#include <cuda_runtime.h>
#include <cuda_bf16.h>
#include <math.h>

// pred[b] = sigmoid(gb + data[b,:].bias + || data[b,:] @ embed ||^2)
//   (the (B,F,F) Gram double-sum collapses to the squared norm of s = x @ V)
//
// Grid = 128 blocks (fg 0..15 x bg 0..7), 256 threads, one wave.
// Block (fg, bg): 8 batch rows x 128 features x all 64 dims.
//   - x tile in smem (float4 reads, 16 LDS.128/thread)
//   - REDUCE-SCATTER butterfly over the 16 feature slices: live value set
//     halves every round (30 SHFL + 30 SEL + 30 ADD vs 128 SHFL + 128 ADD)
//   - emission: 2 full-warp REDG.ADD (spread addresses) per warp
//   - hierarchical finish: one acq_rel ticket per batch group (8 counters on
//     distinct 128B lines); the 16th block of a group finishes its 8 rows
//     (2KB readback) and resets its slice + counter (replay-deterministic).

#define F_NUM   2048
#define D_DIM   64
#define BATCH   64
#define THREADS 256
#define BGC     8          // batch groups (8 rows each)
#define FGC     16         // feature groups per batch group
#define FPB     128        // features per block
#define BPB     8          // batch rows per block

__device__ float        g_s[BATCH][D_DIM];   // zero-init; re-zeroed by finishers
__device__ float        g_lin[BATCH];
__device__ unsigned int g_counter[BGC * 32]; // one counter per 128B line

__global__ __launch_bounds__(THREADS, 1)
void KTM_22110491640579_kernel(const float* __restrict__ data,
                               const float* __restrict__ embed,
                               const float* __restrict__ bias,
                               const float* __restrict__ gbias,
                               float* __restrict__ out) {
    __shared__ float4 xs4[BPB][FPB / 4];      // 4 KB x tile [8][32 quads]
    __shared__ unsigned int s_ticket;

    const int tid  = threadIdx.x;
    const int fg   = blockIdx.x & (FGC - 1);  // 0..15
    const int bg   = blockIdx.x >> 4;         // 0..7
    const int f0   = fg * FPB;
    const int b0   = bg * BPB;
    const int w    = tid >> 5;                // warp 0..7
    const int lane = tid & 31;

    // ---- prefetch bias for the linear term (overlaps with x staging) ----
    float bv[4];
    #pragma unroll
    for (int k = 0; k < 4; ++k) bv[k] = bias[f0 + lane + 32 * k];

    // ---- stage x tile: 8 rows x 128 floats, one float4 per thread ----
    xs4[w][lane] = ((const float4*)(data + (size_t)(b0 + w) * F_NUM + f0))[lane];
    __syncthreads();

    // ---- main loop ----
    // dq = half-warp-selected quad of the 64-dim s vector (16 quads total)
    // fs = lane bits 0..3 -> 16 slices x 8 features
    const int dq = (w << 1) | (lane >> 4);    // 0..15
    const int fs = lane & 15;                 // 0..15
    const float4* V4 = ((const float4*)embed) + ((size_t)(f0 + fs * 8) * 16 + dq);

    // v[b*4+c] accumulates s-component dq*4+c for batch row b
    float v[32];
    #pragma unroll
    for (int i = 0; i < 32; ++i) v[i] = 0.f;

    #pragma unroll
    for (int jq = 0; jq < 2; ++jq) {          // two float4 groups of 4 features
        float4 xr[BPB];
        #pragma unroll
        for (int b = 0; b < BPB; ++b)
            xr[b] = xs4[b][fs * 2 + jq];      // LDS.128, half-warp broadcast
        #pragma unroll
        for (int jj = 0; jj < 4; ++jj) {
            const float4 vv = V4[(size_t)(jq * 4 + jj) * 16];  // L2-hot
            #pragma unroll
            for (int b = 0; b < BPB; ++b) {
                const float x = (jj == 0) ? xr[b].x :
                                (jj == 1) ? xr[b].y :
                                (jj == 2) ? xr[b].z : xr[b].w;
                v[b * 4 + 0] = fmaf(x, vv.x, v[b * 4 + 0]);
                v[b * 4 + 1] = fmaf(x, vv.y, v[b * 4 + 1]);
                v[b * 4 + 2] = fmaf(x, vv.z, v[b * 4 + 2]);
                v[b * 4 + 3] = fmaf(x, vv.w, v[b * 4 + 3]);
            }
        }
    }

    // ---- linear term: warp w handles batch row w, full-warp shfl reduce ----
    {
        const float* xsf = (const float*)xs4; // [b][f], stride 128
        float l = 0.f;
        #pragma unroll
        for (int k = 0; k < 4; ++k)
            l = fmaf(xsf[w * FPB + lane + 32 * k], bv[k], l);
        #pragma unroll
        for (int off = 16; off >= 1; off >>= 1)
            l += __shfl_down_sync(0xffffffffu, l, off);
        if (lane == 0) atomicAdd(&g_lin[b0 + w], l);  // relaxed RED.ADD
    }

    // ---- reduce-scatter over fs (lane bits 0..3): live set halves/round ----
    // After the 4 rounds, lane fs holds f = fs*2 + {0,1} in bit-reversed
    // window order: batch row fs>>1, components (fs&1)*2 + {0,1} of quad dq.
    #pragma unroll
    for (int off = 8, n = 16; off >= 1; off >>= 1, n >>= 1) {
        const bool up = (fs & off) != 0;
        #pragma unroll
        for (int i = 0; i < 16; ++i) {        // only i < n is live
            if (i < n) {
                const float s = up ? v[i + n] : v[i];
                v[i] = s + __shfl_xor_sync(0xffffffffu, s, off);
            }
        }
    }
    {
        float* dst = &g_s[b0 + (fs >> 1)][dq * 4 + (fs & 1) * 2];
        atomicAdd(dst + 0, v[0]);             // full-warp spread REDG.ADD
        atomicAdd(dst + 1, v[1]);
    }

    // ---- per-group acq_rel ticket (release our REDs / acquire others') ----
    __syncthreads();
    if (tid == 0) {
        unsigned int old;
        asm volatile("atom.acq_rel.gpu.global.add.u32 %0, [%1], 1;"
                     : "=r"(old) : "l"(&g_counter[bg * 32]) : "memory");
        s_ticket = old;
    }
    __syncthreads();
    if (s_ticket != (unsigned)(FGC - 1)) return;

    // ---- group finisher: 8 rows of THIS batch group only (2KB readback) ----
    {
        const int b = b0 + w;                 // warp w -> batch row b0+w
        const float2 sv = __ldcg(((const float2*)g_s[b]) + lane);
        float ss = fmaf(sv.x, sv.x, sv.y * sv.y);
        #pragma unroll
        for (int off = 16; off >= 1; off >>= 1)
            ss += __shfl_down_sync(0xffffffffu, ss, off);
        if (lane == 0) {
            const float z = __ldcg(&gbias[0]) + __ldcg(&g_lin[b]) + ss;
            out[b] = 1.0f / (1.0f + __expf(-z));
            g_lin[b] = 0.f;                   // reset for next replay
        }
        if (lane < 16)                        // reset s slice (16 float4)
            ((float4*)g_s[b])[lane] = make_float4(0.f, 0.f, 0.f, 0.f);
        if (tid == 0) g_counter[bg * 32] = 0u;
    }
}

extern "C" void kernel_launch(void* const* d_in, const int* in_sizes, int n_in,
                              void* d_out, int out_size) {
    const float* data  = (const float*)d_in[0];   // (64, 2048)
    const float* embed = (const float*)d_in[1];   // (2048, 64)
    const float* bias  = (const float*)d_in[2];   // (2048, 1)
    const float* gb    = (const float*)d_in[3];   // (1, 1)
    float* out = (float*)d_out;                   // (64,)
    (void)in_sizes; (void)n_in; (void)out_size;

    KTM_22110491640579_kernel<<<FGC * BGC, THREADS>>>(data, embed, bias, gb, out);
}

// round 10
// speedup vs baseline: 1.2330x; 1.1183x over previous
#include <cuda_runtime.h>
#include <cuda_bf16.h>
#include <math.h>

// pred[b] = sigmoid(gb + data[b,:].bias + || data[b,:] @ embed ||^2)
//   (the (B,F,F) Gram double-sum collapses to the squared norm of s = x @ V)
//
// Grid = 128 blocks (fg 0..15 x bg 0..7), 256 threads, one wave.
// Block (fg, bg): 8 batch rows x 128 features x all 64 dims.
//   - ALL global loads front-batched (8 embed LDG.128 + 4 bias + 1 x) so the
//     ~250cyc L2 latency overlaps the x STS/BAR drain (MLP_p1 ~13)
//   - x tile in smem (float4 reads); reduce-scatter butterfly over the 16
//     feature slices (live set halves per round); 2 full-warp REDG.ADD emit
//   - hierarchical finish: one acq_rel ticket per batch group (8 counters on
//     distinct 128B lines); the 16th block of a group finishes its 8 rows
//     (2KB readback) and resets its slice + counter (replay-deterministic).

#define F_NUM   2048
#define D_DIM   64
#define BATCH   64
#define THREADS 256
#define BGC     8          // batch groups (8 rows each)
#define FGC     16         // feature groups per batch group
#define FPB     128        // features per block
#define BPB     8          // batch rows per block

__device__ float        g_s[BATCH][D_DIM];   // zero-init; re-zeroed by finishers
__device__ float        g_lin[BATCH];
__device__ unsigned int g_counter[BGC * 32]; // one counter per 128B line

__global__ __launch_bounds__(THREADS, 1)
void KTM_22110491640579_kernel(const float* __restrict__ data,
                               const float* __restrict__ embed,
                               const float* __restrict__ bias,
                               const float* __restrict__ gbias,
                               float* __restrict__ out) {
    __shared__ float4 xs4[BPB][FPB / 4];      // 4 KB x tile [8][32 quads]
    __shared__ unsigned int s_ticket;

    const int tid  = threadIdx.x;
    const int fg   = blockIdx.x & (FGC - 1);  // 0..15
    const int bg   = blockIdx.x >> 4;         // 0..7
    const int f0   = fg * FPB;
    const int b0   = bg * BPB;
    const int w    = tid >> 5;                // warp 0..7
    const int lane = tid & 31;

    const int dq = (w << 1) | (lane >> 4);    // 0..15: quad of the s vector
    const int fs = lane & 15;                 // 0..15: 8-feature slice
    const float4* V4 = ((const float4*)embed) + ((size_t)(f0 + fs * 8) * 16 + dq);

    // ---- front-batch ALL global loads (independent addresses, MLP ~13) ----
    float4 ev[8];                             // embed quads for this thread
    #pragma unroll
    for (int j = 0; j < 8; ++j) ev[j] = V4[(size_t)j * 16];
    float bv[4];                              // bias slice for the linear term
    #pragma unroll
    for (int k = 0; k < 4; ++k) bv[k] = bias[f0 + lane + 32 * k];
    const float4 xq =                         // this thread's x quad
        ((const float4*)(data + (size_t)(b0 + w) * F_NUM + f0))[lane];

    // ---- stage x tile: 8 rows x 128 floats ----
    xs4[w][lane] = xq;
    __syncthreads();

    // ---- main loop: v[b*4+c] accumulates s[dq*4+c] for batch row b ----
    float v[32];
    #pragma unroll
    for (int i = 0; i < 32; ++i) v[i] = 0.f;

    #pragma unroll
    for (int jq = 0; jq < 2; ++jq) {          // two float4 groups of 4 features
        float4 xr[BPB];
        #pragma unroll
        for (int b = 0; b < BPB; ++b)
            xr[b] = xs4[b][fs * 2 + jq];      // LDS.128, half-warp broadcast
        #pragma unroll
        for (int jj = 0; jj < 4; ++jj) {
            const float4 vv = ev[jq * 4 + jj];
            #pragma unroll
            for (int b = 0; b < BPB; ++b) {
                const float x = (jj == 0) ? xr[b].x :
                                (jj == 1) ? xr[b].y :
                                (jj == 2) ? xr[b].z : xr[b].w;
                v[b * 4 + 0] = fmaf(x, vv.x, v[b * 4 + 0]);
                v[b * 4 + 1] = fmaf(x, vv.y, v[b * 4 + 1]);
                v[b * 4 + 2] = fmaf(x, vv.z, v[b * 4 + 2]);
                v[b * 4 + 3] = fmaf(x, vv.w, v[b * 4 + 3]);
            }
        }
    }

    // ---- linear term: warp w handles batch row w, full-warp shfl reduce ----
    {
        const float* xsf = (const float*)xs4; // [b][f], stride 128
        float l = 0.f;
        #pragma unroll
        for (int k = 0; k < 4; ++k)
            l = fmaf(xsf[w * FPB + lane + 32 * k], bv[k], l);
        #pragma unroll
        for (int off = 16; off >= 1; off >>= 1)
            l += __shfl_down_sync(0xffffffffu, l, off);
        if (lane == 0) atomicAdd(&g_lin[b0 + w], l);  // relaxed RED.ADD
    }

    // ---- reduce-scatter over fs (lane bits 0..3): live set halves/round ----
    // After the 4 rounds, lane fs holds batch row fs>>1, components
    // (fs&1)*2 + {0,1} of its dq quad.
    #pragma unroll
    for (int off = 8, n = 16; off >= 1; off >>= 1, n >>= 1) {
        const bool up = (fs & off) != 0;
        #pragma unroll
        for (int i = 0; i < 16; ++i) {        // only i < n is live
            if (i < n) {
                const float s = up ? v[i + n] : v[i];
                v[i] = s + __shfl_xor_sync(0xffffffffu, s, off);
            }
        }
    }
    {
        float* dst = &g_s[b0 + (fs >> 1)][dq * 4 + (fs & 1) * 2];
        atomicAdd(dst + 0, v[0]);             // full-warp spread REDG.ADD
        atomicAdd(dst + 1, v[1]);
    }

    // ---- per-group acq_rel ticket (release our REDs / acquire others') ----
    __syncthreads();
    if (tid == 0) {
        unsigned int old;
        asm volatile("atom.acq_rel.gpu.global.add.u32 %0, [%1], 1;"
                     : "=r"(old) : "l"(&g_counter[bg * 32]) : "memory");
        s_ticket = old;
    }
    __syncthreads();
    if (s_ticket != (unsigned)(FGC - 1)) return;

    // ---- group finisher: 8 rows of THIS batch group only (2KB readback) ----
    {
        const int b = b0 + w;                 // warp w -> batch row b0+w
        // prefetch the scalar tail loads so they overlap the s readback
        const float lin_b = __ldcg(&g_lin[b]);
        const float gb    = __ldcg(&gbias[0]);
        const float2 sv   = __ldcg(((const float2*)g_s[b]) + lane);
        float ss = fmaf(sv.x, sv.x, sv.y * sv.y);
        #pragma unroll
        for (int off = 16; off >= 1; off >>= 1)
            ss += __shfl_down_sync(0xffffffffu, ss, off);
        if (lane == 0) {
            const float z = gb + lin_b + ss;
            out[b] = 1.0f / (1.0f + __expf(-z));
            g_lin[b] = 0.f;                   // reset for next replay
        }
        if (lane < 16)                        // reset s slice (16 float4)
            ((float4*)g_s[b])[lane] = make_float4(0.f, 0.f, 0.f, 0.f);
        if (tid == 0) g_counter[bg * 32] = 0u;
    }
}

extern "C" void kernel_launch(void* const* d_in, const int* in_sizes, int n_in,
                              void* d_out, int out_size) {
    const float* data  = (const float*)d_in[0];   // (64, 2048)
    const float* embed = (const float*)d_in[1];   // (2048, 64)
    const float* bias  = (const float*)d_in[2];   // (2048, 1)
    const float* gb    = (const float*)d_in[3];   // (1, 1)
    float* out = (float*)d_out;                   // (64,)
    (void)in_sizes; (void)n_in; (void)out_size;

    KTM_22110491640579_kernel<<<FGC * BGC, THREADS>>>(data, embed, bias, gb, out);
}